// round 12
// baseline (speedup 1.0000x reference)
#include <cuda_runtime.h>
#include <cstdint>

// GlobalNHC: Nose-Hoover chain thermostat, B=32, N=131072, D=3, C=5, NRESPA=2 x 7 SY.
// Persistent kernel, 148 blocks x 1024 threads (1 CTA/SM, ALL SMs populated).
// Flat range partition decoupled from batches: each block owns 21 float4/thread of
// the flat [B*N*D/4] array (<=2 batches per block); KE split into two per-batch
// buckets; global ticket sync; warps 0/1 scan partials + run the two chains;
// phase3 rescale with per-element batch-scale select.
//
// mom enters the integrator only via KE = sum(mom^2/mas) and a uniform per-batch
// rescale, so the 14 substeps collapse to scalar chain math with KE *= s^2.

#define BB     32
#define NATM   131072
#define DDIM   3
#define CCH    5
#define NPER   (NATM * DDIM)        // 393216 floats per batch
#define NVEC   (NPER / 4)           // 98304 float4 per batch
#define TOTF4  (BB * NVEC)          // 3145728 float4 total
#define NBLK   148
#define TPB    1024
#define V4PT   21                   // float4 per thread (full block)
#define BLKF4  (TPB * V4PT)         // 21504 float4 per block
#define SSTG   14                   // float4s per thread staged in smem
#define SMEM_DYN (SSTG * TPB * 16)  // 229376 B
#define NRESPA_ 2
#define LOG2E  1.4426950408889634f

__device__ double       g_eA[NBLK];   // per-block KE partial for its batchA
__device__ double       g_eB[NBLK];   // per-block KE partial for its batchB
__device__ unsigned int g_bar;        // monotonic arrival counter (never reset)

__device__ __forceinline__ void st_stream(float4* p, float4 v) {
    asm volatile("st.global.cs.v4.f32 [%0], {%1,%2,%3,%4};"
                 :: "l"(p), "f"(v.x), "f"(v.y), "f"(v.z), "f"(v.w) : "memory");
}

__device__ __forceinline__ float ex2_approx(float x) {   // 2^x via MUFU.EX2
    float r;
    asm("ex2.approx.f32 %0, %1;" : "=f"(r) : "f"(x));
    return r;
}

__device__ __forceinline__ uint32_t smem_u32(const void* p) {
    uint32_t a;
    asm("{ .reg .u64 t; cvta.to.shared.u64 t, %1; cvt.u32.u64 %0, t; }"
        : "=r"(a) : "l"(p));
    return a;
}

// KE contribution of float4 v at flat float4-index L (mas is the flat [B*N] array)
__device__ __forceinline__ float ke_contrib(float4 v, unsigned L,
                                            const float* __restrict__ mas) {
    const unsigned E = 4u * L;
    const unsigned a = __umulhi(E, 0xAAAAAAABu) >> 1;   // E/3 (global atom idx)
    const unsigned r = E - 3u * a;                      // E%3
    float p  = v.x * v.x, q  = v.y * v.y;
    float u  = v.z * v.z, w2 = v.w * v.w;
    float cA = p, cB = w2;
    if (r < 2u)  cA += q; else cB += q;
    if (r == 0u) cA += u; else cB += u;
    return __fdividef(cA, mas[a]) + __fdividef(cB, mas[a + 1]);
}

// Full 14-substep chain for batch b given total KE. Returns cumulative scale;
// writes nhc outputs if owner.
__device__ float run_chain(int b, double ked,
                           const float* __restrict__ kbt,
                           const float* __restrict__ dtm,
                           const float* __restrict__ pos_nhc,
                           const float* __restrict__ mom_nhc,
                           const float* __restrict__ mas_nhc,
                           const float* __restrict__ stp_p,
                           bool owner,
                           float* __restrict__ out_posnhc,
                           float* __restrict__ out_momnhc) {
    const float wts[7] = {
        0.78451361047756f, 0.235573213359357f, -1.17767998417887f,
        (float)(1.0 - 2.0 * (0.78451361047756 + 0.235573213359357 - 1.17767998417887)),
        -1.17767998417887f, 0.235573213359357f, 0.78451361047756f
    };

    const double kgd = (double)kbt[b] * (double)(NATM * DDIM);
    const float  kbT = kbt[b];
    const float  dts = dtm[b] * (stp_p[0] / (float)NRESPA_);

    float pn[CCH], mn[CCH], imq[CCH];
    #pragma unroll
    for (int c = 0; c < CCH; c++) {
        pn[c]  = pos_nhc[b * CCH + c];
        mn[c]  = mom_nhc[b * CCH + c];
        imq[c] = 1.0f / mas_nhc[b * CCH + c];
    }

    double cum = 1.0;
    for (int r = 0; r < NRESPA_; r++) {
        #pragma unroll
        for (int iw = 0; iw < 7; iw++) {
            const float dea   = dts * wts[iw];
            const float dea2  = dea * 0.5f;
            const float dea4L = dea * (0.25f * LOG2E);
            const float deaL  = dea * LOG2E;

            float g[CCH], mc[CCH];
            g[0] = (float)(ked - kgd);
            #pragma unroll
            for (int j = 1; j < CCH; j++)
                g[j] = mn[j - 1] * mn[j - 1] * imq[j - 1] - kbT;

            #pragma unroll
            for (int c = 0; c < CCH; c++) mc[c] = mn[c];
            mc[CCH - 1] += g[CCH - 1] * dea2;

            #pragma unroll
            for (int j = CCH - 2; j >= 0; j--) {
                float f = ex2_approx(-mc[j + 1] * imq[j + 1] * dea4L);
                mc[j] = (mc[j] * f + g[j] * dea2) * f;
            }

            #pragma unroll
            for (int c = 0; c < CCH; c++) pn[c] += mc[c] * imq[c] * dea;

            const float s = ex2_approx(-mc[0] * imq[0] * deaL);
            cum *= (double)s;
            ked *= (double)s * (double)s;

            g[0] = (float)(ked - kgd);
            #pragma unroll
            for (int j = CCH - 2; j >= 0; j--) {
                float f = ex2_approx(-mc[j + 1] * imq[j + 1] * dea4L);
                mc[j] = (mc[j] * f + g[j] * dea2) * f;
            }
            mc[CCH - 1] += g[CCH - 1] * dea2;

            #pragma unroll
            for (int c = 0; c < CCH; c++) mn[c] = mc[c];
        }
    }

    if (owner) {
        #pragma unroll
        for (int c = 0; c < CCH; c++) {
            out_posnhc[b * CCH + c] = pn[c];
            out_momnhc[b * CCH + c] = mn[c];
        }
    }
    return (float)cum;
}

__global__ void __launch_bounds__(TPB, 1)
nhc_fused_kernel(const float4* __restrict__ mom4,
                 const float*  __restrict__ mas,
                 const float*  __restrict__ kbt,
                 const float*  __restrict__ dtm,
                 const float*  __restrict__ pos_nhc,
                 const float*  __restrict__ mom_nhc,
                 const float*  __restrict__ mas_nhc,
                 const float*  __restrict__ stp_p,
                 float4* __restrict__ out_mom4,
                 float*  __restrict__ out_posnhc,
                 float*  __restrict__ out_momnhc) {
    extern __shared__ float4 s_stage[];        // SSTG * TPB float4s
    const int blk = blockIdx.x;
    const int t   = threadIdx.x;

    const int base = blk * BLKF4;
    const int rem  = TOTF4 - base;
    const int kmax = (rem <= 0) ? 0 : (rem >= BLKF4 ? V4PT : rem / TPB);
    const int kstg = (kmax < SSTG) ? kmax : SSTG;
    const int batchA  = (kmax > 0) ? (base / NVEC) : 0;
    const int boundF4 = (batchA + 1) * NVEC;
    const int endF4   = base + kmax * TPB;
    const bool hasB   = endF4 > boundF4;

    const uint32_t sbase = smem_u32(s_stage);

    // ---------------- Phase 1: KE partials (two batch buckets) -------------
    float accA = 0.0f, accB = 0.0f;

    if (kmax == V4PT) {                          // fast path: 146/148 blocks
        #pragma unroll
        for (int k = 0; k < SSTG; k++) {
            const uint32_t saddr = sbase + (uint32_t)(k * TPB + t) * 16u;
            const float4* gaddr = &mom4[base + k * TPB + t];
            asm volatile("cp.async.cg.shared.global [%0], [%1], 16;"
                         :: "r"(saddr), "l"(gaddr) : "memory");
        }
        asm volatile("cp.async.commit_group;" ::: "memory");

        float4 buf[V4PT - SSTG];                 // 7 float4 LDG half
        #pragma unroll
        for (int j = 0; j < V4PT - SSTG; j++)
            buf[j] = mom4[base + (SSTG + j) * TPB + t];
        #pragma unroll
        for (int j = 0; j < V4PT - SSTG; j++) {
            const int L = base + (SSTG + j) * TPB + t;
            float c = ke_contrib(buf[j], (unsigned)L, mas);
            if (L < boundF4) accA += c; else accB += c;
        }

        asm volatile("cp.async.wait_group 0;" ::: "memory");
        #pragma unroll 7
        for (int k = 0; k < SSTG; k++) {
            const int L = base + k * TPB + t;
            float c = ke_contrib(s_stage[k * TPB + t], (unsigned)L, mas);
            if (L < boundF4) accA += c; else accB += c;
        }
    } else if (kmax > 0) {                       // tail block (uniform k bound)
        for (int k = 0; k < kstg; k++) {
            const uint32_t saddr = sbase + (uint32_t)(k * TPB + t) * 16u;
            const float4* gaddr = &mom4[base + k * TPB + t];
            asm volatile("cp.async.cg.shared.global [%0], [%1], 16;"
                         :: "r"(saddr), "l"(gaddr) : "memory");
        }
        asm volatile("cp.async.commit_group;" ::: "memory");
        for (int k = SSTG; k < kmax; k++) {
            const int L = base + k * TPB + t;
            float c = ke_contrib(mom4[L], (unsigned)L, mas);
            if (L < boundF4) accA += c; else accB += c;
        }
        asm volatile("cp.async.wait_group 0;" ::: "memory");
        for (int k = 0; k < kstg; k++) {
            const int L = base + k * TPB + t;
            float c = ke_contrib(s_stage[k * TPB + t], (unsigned)L, mas);
            if (L < boundF4) accA += c; else accB += c;
        }
    }

    // warp reduce both buckets, then cross-warp in double
    #pragma unroll
    for (int off = 16; off > 0; off >>= 1) {
        accA += __shfl_down_sync(0xffffffffu, accA, off);
        accB += __shfl_down_sync(0xffffffffu, accB, off);
    }

    __shared__ double s_wA[TPB / 32], s_wB[TPB / 32];
    __shared__ float  s_scales[2];
    const int wid = t >> 5, lid = t & 31;
    if (lid == 0) { s_wA[wid] = (double)accA; s_wB[wid] = (double)accB; }
    __syncthreads();

    if (t == 0) {
        double tA = 0.0, tB = 0.0;
        #pragma unroll
        for (int i = 0; i < TPB / 32; i++) { tA += s_wA[i]; tB += s_wB[i]; }
        g_eA[blk] = tA;
        g_eB[blk] = tB;
        __threadfence();

        // ---------------- Global ticket sync (148 blocks, replay-safe) -----
        unsigned int ticket = atomicAdd(&g_bar, 1u);
        unsigned int target = (ticket / NBLK + 1u) * NBLK;
        while (*((volatile unsigned int*)&g_bar) < target) __nanosleep(32);
        __threadfence();
    }
    __syncthreads();

    // ------- Phase 2: warps 0/1 scan partials and run the two chains -------
    if (wid < 2) {
        const int  tgt    = (wid == 0) ? batchA : batchA + 1;
        const bool active = (wid == 0) ? (kmax > 0) : hasB;
        if (active) {
            double ke = 0.0;
            for (int j = lid; j < NBLK; j += 32) {
                const int bJ = j * BLKF4;
                if (bJ >= TOTF4) continue;
                const int remJ = TOTF4 - bJ;
                const int kmJ  = (remJ >= BLKF4) ? V4PT : remJ / TPB;
                const int idAJ = bJ / NVEC;
                if (idAJ == tgt) ke += g_eA[j];
                const int endJ = bJ + kmJ * TPB;
                if (endJ > (idAJ + 1) * NVEC && idAJ + 1 == tgt) ke += g_eB[j];
            }
            #pragma unroll
            for (int off = 16; off > 0; off >>= 1)
                ke += __shfl_down_sync(0xffffffffu, ke, off);

            if (lid == 0) {
                // warp0 owns batchA iff batchA starts exactly at this block's base;
                // warp1 always owns batchB (its start lies inside this block).
                const bool owner = (wid == 1) || (batchA * NVEC == base);
                s_scales[wid] = run_chain(tgt, ke, kbt, dtm, pos_nhc, mom_nhc,
                                          mas_nhc, stp_p, owner,
                                          out_posnhc, out_momnhc);
            }
        }
    }
    __syncthreads();

    // ------- Phase 3: rescale with per-element batch-scale select ----------
    const float sA = s_scales[0];
    const float sB = s_scales[1];

    if (kmax == V4PT) {
        #pragma unroll 7
        for (int k = 0; k < SSTG; k++) {
            const int L = base + k * TPB + t;
            float4 v = s_stage[k * TPB + t];
            const float s = (L < boundF4) ? sA : sB;
            v.x *= s; v.y *= s; v.z *= s; v.w *= s;
            st_stream(out_mom4 + L, v);
        }
        #pragma unroll
        for (int k = SSTG; k < V4PT; k++) {
            const int L = base + k * TPB + t;
            float4 v = mom4[L];
            const float s = (L < boundF4) ? sA : sB;
            v.x *= s; v.y *= s; v.z *= s; v.w *= s;
            st_stream(out_mom4 + L, v);
        }
    } else if (kmax > 0) {
        for (int k = 0; k < kstg; k++) {
            const int L = base + k * TPB + t;
            float4 v = s_stage[k * TPB + t];
            const float s = (L < boundF4) ? sA : sB;
            v.x *= s; v.y *= s; v.z *= s; v.w *= s;
            st_stream(out_mom4 + L, v);
        }
        for (int k = SSTG; k < kmax; k++) {
            const int L = base + k * TPB + t;
            float4 v = mom4[L];
            const float s = (L < boundF4) ? sA : sB;
            v.x *= s; v.y *= s; v.z *= s; v.w *= s;
            st_stream(out_mom4 + L, v);
        }
    }
}

// ---------------------------------------------------------------------------
extern "C" void kernel_launch(void* const* d_in, const int* in_sizes, int n_in,
                              void* d_out, int out_size) {
    // inputs: 0 pos, 1 mom, 2 mas, 3 kbt, 4 dtm, 5 pos_nhc, 6 mom_nhc, 7 mas_nhc, 8 stp
    const float* mom     = (const float*)d_in[1];
    const float* mas     = (const float*)d_in[2];
    const float* kbt     = (const float*)d_in[3];
    const float* dtm     = (const float*)d_in[4];
    const float* pos_nhc = (const float*)d_in[5];
    const float* mom_nhc = (const float*)d_in[6];
    const float* mas_nhc = (const float*)d_in[7];
    const float* stp     = (const float*)d_in[8];

    float* out = (float*)d_out;
    float* out_mom    = out;                          // [B, N, D]
    float* out_posnhc = out + (size_t)BB * NPER;      // [B, C]
    float* out_momnhc = out_posnhc + BB * CCH;        // [B, C]

    static int attr_done = 0;
    if (!attr_done) {
        cudaFuncSetAttribute(nhc_fused_kernel,
                             cudaFuncAttributeMaxDynamicSharedMemorySize,
                             SMEM_DYN);
        attr_done = 1;
    }

    nhc_fused_kernel<<<NBLK, TPB, SMEM_DYN>>>(
        (const float4*)mom, mas,
        kbt, dtm, pos_nhc, mom_nhc, mas_nhc, stp,
        (float4*)out_mom, out_posnhc, out_momnhc);
}